// round 17
// baseline (speedup 1.0000x reference)
#include <cuda_runtime.h>
#include <cstddef>

// Problem constants (fixed by the reference)
#define BB 8
#define DD 32
#define NPIX 262144          // 512*512
#define KK 16

#define P1_CHUNK  8192
#define P1_NCHUNK (NPIX / P1_CHUNK)    // 32 chunks; x2 dg = 64 pass1 blocks/img
#define P2_BLOCKS (NPIX / 4 / 512)     // 128 pass2 blocks/img (512 thr each)

// Scratch (no cudaMalloc). Zeroed by k_zero each call.
__device__ float g_sums[BB * KK * DD];
__device__ float g_counts[BB * KK];

// ---------------------------------------------------------------------------
__global__ void k_zero(float* out) {
    int tid = threadIdx.x;
    for (int j = tid; j < BB * KK * DD; j += 512) g_sums[j] = 0.0f;
    if (tid < BB * KK) g_counts[tid] = 0.0f;
    if (tid == 0) out[0] = 0.0f;
}

// ---------------------------------------------------------------------------
// Mixed kernel: blocks [0, nP1) run pass1 for image b1 (R16 body: per-lane
// privatized smem bins, software pipeline dist 1, distributed up-front
// counting); blocks [nP1, nP1+128) run pass2 for image b2, whose embedding
// stream was loaded into L2 by pass1(b2) exactly ONE LAUNCH earlier ->
// pass2 reads are L2 hits while pass1(b1) streams fresh DRAM. Means are
// computed in-block from g_sums/g_counts (finalize kernel eliminated);
// pass2 block 0 also adds the pairwise push + regularization losses.
// ---------------------------------------------------------------------------
__global__ __launch_bounds__(512, 4) void k_mix(const float* __restrict__ emb,
                                                const int* __restrict__ gt,
                                                float* out, int b1, int b2) {
    __shared__ float sm[10752];   // 43 KB, carved per role
    const int tid = threadIdx.x;
    const int w   = tid >> 5;
    const int lane = tid & 31;
    const int nP1 = (b1 >= 0) ? 2 * P1_NCHUNK : 0;

    if ((int)blockIdx.x < nP1) {
        // ================= pass1 part (image b1) =================
        float*    acc  = sm;                         // 8192 f
        float*    cnt  = sm + 8192;                  // 512 f
        unsigned* labw = (unsigned*)(sm + 8704);     // 2048 u32

        const int c  = blockIdx.x >> 1;
        const int dg = blockIdx.x & 1;
        const int p0 = c * P1_CHUNK;
        const int d  = dg * 16 + w;
        const int b  = b1;

        for (int j = tid; j < 8192; j += 512) acc[j] = 0.0f;
        if (tid < 512) cnt[tid] = 0.0f;

        const int4* g4 = (const int4*)(gt + (size_t)b * NPIX + p0);
        for (int j = tid; j < P1_CHUNK / 4; j += 512) {
            int4 t = g4[j];
            labw[j] = (unsigned)t.x | ((unsigned)t.y << 8) |
                      ((unsigned)t.z << 16) | ((unsigned)t.w << 24);
        }
        __syncthreads();

        if (dg == 0) {
            #pragma unroll
            for (int j = 0; j < 4; j++) {
                unsigned kw = labw[j * 512 + tid];
                atomicAdd(&cnt[(int)(kw & 15u) * 32 + lane], 1.0f);
                atomicAdd(&cnt[(int)((kw >> 8) & 15u) * 32 + lane], 1.0f);
                atomicAdd(&cnt[(int)((kw >> 16) & 15u) * 32 + lane], 1.0f);
                atomicAdd(&cnt[(int)(kw >> 24) * 32 + lane], 1.0f);
            }
        }

        const float4* e4 = (const float4*)(emb + ((size_t)(b * DD + d)) * NPIX + p0);
        float* aw = acc + (w * KK) * 32 + lane;

        #define RMW(V, KW) do {                                          \
            unsigned kw_ = (KW);                                         \
            aw[(int)(kw_ & 15u) * 32]         += (V).x;                  \
            aw[(int)((kw_ >> 8) & 15u) * 32]  += (V).y;                  \
            aw[(int)((kw_ >> 16) & 15u) * 32] += (V).z;                  \
            aw[(int)(kw_ >> 24) * 32]         += (V).w;                  \
        } while (0)

        float4 va = __ldg(&e4[lane]);
        float4 vb = __ldg(&e4[lane + 32]);
        unsigned ka = labw[lane];
        unsigned kb = labw[lane + 32];

        #pragma unroll 1
        for (int i = 0; i < 31; i++) {
            const int nidx = (i + 1) * 64 + lane;
            float4 na = __ldg(&e4[nidx]);
            float4 nb = __ldg(&e4[nidx + 32]);
            unsigned nka = labw[nidx];
            unsigned nkb = labw[nidx + 32];
            RMW(va, ka);
            RMW(vb, kb);
            va = na; vb = nb; ka = nka; kb = nkb;
        }
        RMW(va, ka);
        RMW(vb, kb);
        #undef RMW
        __syncwarp();

        // Per-warp epilogue: reduce each k-row (contiguous 128B), atomicAdd
        // into g_sums (512 spread atomics per image -> negligible).
        {
            const int k = lane >> 1;
            const int h = lane & 1;
            const float4* row = (const float4*)(acc + ((w * KK + k) << 5) + (h << 4));
            float4 r0 = row[0], r1 = row[1], r2 = row[2], r3 = row[3];
            float s = ((r0.x + r0.y) + (r0.z + r0.w)) + ((r1.x + r1.y) + (r1.z + r1.w))
                    + ((r2.x + r2.y) + (r2.z + r2.w)) + ((r3.x + r3.y) + (r3.z + r3.w));
            s += __shfl_down_sync(0xffffffffu, s, 1);
            if (h == 0)
                atomicAdd(&g_sums[(b * KK + k) * DD + d], s);
        }
        if (dg == 0) {
            __syncthreads();                 // block-uniform condition: legal
            if (w == 0) {
                const int k = lane >> 1;
                const int h = lane & 1;
                const float4* row = (const float4*)(cnt + (k << 5) + (h << 4));
                float4 r0 = row[0], r1 = row[1], r2 = row[2], r3 = row[3];
                float s = ((r0.x + r0.y) + (r0.z + r0.w)) + ((r1.x + r1.y) + (r1.z + r1.w))
                        + ((r2.x + r2.y) + (r2.z + r2.w)) + ((r3.x + r3.y) + (r3.z + r3.w));
                s += __shfl_down_sync(0xffffffffu, s, 1);
                if (h == 0)
                    atomicAdd(&g_counts[b * KK + k], s);
            }
        }
    } else if (b2 >= 0) {
        // ================= pass2 part (image b2) =================
        const int pidx = blockIdx.x - nP1;
        const int b = b2;
        float* m   = sm;           // 528 (padded 33-stride)
        float* wk  = sm + 528;     // 16
        float* red = sm + 544;     // 16

        // Means from g_sums/g_counts (pass1(b2) completed last launch).
        {
            const int k = tid >> 5, dd = tid & 31;
            float cv = fmaxf(g_counts[b * KK + k], 1.0f);
            m[k * 33 + dd] = g_sums[b * 512 + tid] / cv;
        }
        if (tid < KK)
            wk[tid] = 1.0f / ((float)KK * fmaxf(g_counts[b * KK + tid], 1.0f));
        __syncthreads();

        // Designated block: pairwise push loss + regularization (once/image).
        if (pidx == 0 && tid < 256) {
            const int i = tid >> 4, j = tid & 15;
            float v = 0.0f;
            if (j > i) {
                float d2 = 0.0f;
                #pragma unroll
                for (int dd = 0; dd < DD; dd++) {
                    float df = m[i * 33 + dd] - m[j * 33 + dd];
                    d2 = fmaf(df, df, d2);
                }
                float pd = sqrtf(d2);
                float h = fmaxf(3.0f - pd, 0.0f);
                v = h * h * (1.0f / (KK * (KK - 1)));
            }
            if (tid < KK) {
                float n2 = 0.0f;
                #pragma unroll
                for (int dd = 0; dd < DD; dd++) {
                    float t = m[tid * 33 + dd];
                    n2 = fmaf(t, t, n2);
                }
                v += 0.001f * sqrtf(n2) * (1.0f / KK);
            }
            #pragma unroll
            for (int off = 16; off; off >>= 1)
                v += __shfl_down_sync(0xffffffffu, v, off);
            if (lane == 0) atomicAdd(out, v * (1.0f / BB));
        }

        const float4* e4 = (const float4*)(emb + (size_t)b * DD * NPIX);
        const int p4 = pidx * 512 + tid;
        const int4 kk = __ldg(&((const int4*)(gt + (size_t)b * NPIX))[p4]);

        const float* m0 = m + kk.x * 33;
        const float* m1 = m + kk.y * 33;
        const float* m2 = m + kk.z * 33;
        const float* m3 = m + kk.w * 33;

        float a0 = 0.0f, a1 = 0.0f, a2 = 0.0f, a3 = 0.0f;
        #pragma unroll
        for (int g = 0; g < 8; g++) {
            float4 v[4];
            #pragma unroll
            for (int j = 0; j < 4; j++)
                v[j] = __ldcs(&e4[(size_t)(g * 4 + j) * (NPIX / 4) + p4]);
            #pragma unroll
            for (int j = 0; j < 4; j++) {
                const int dd = g * 4 + j;
                float t;
                t = v[j].x - m0[dd]; a0 = fmaf(t, t, a0);
                t = v[j].y - m1[dd]; a1 = fmaf(t, t, a1);
                t = v[j].z - m2[dd]; a2 = fmaf(t, t, a2);
                t = v[j].w - m3[dd]; a3 = fmaf(t, t, a3);
            }
        }

        float h, lacc = 0.0f;
        h = fmaxf(sqrtf(a0) - 0.5f, 0.0f); lacc = fmaf(h * h, wk[kk.x], lacc);
        h = fmaxf(sqrtf(a1) - 0.5f, 0.0f); lacc = fmaf(h * h, wk[kk.y], lacc);
        h = fmaxf(sqrtf(a2) - 0.5f, 0.0f); lacc = fmaf(h * h, wk[kk.z], lacc);
        h = fmaxf(sqrtf(a3) - 0.5f, 0.0f); lacc = fmaf(h * h, wk[kk.w], lacc);

        #pragma unroll
        for (int off = 16; off; off >>= 1)
            lacc += __shfl_down_sync(0xffffffffu, lacc, off);
        if (lane == 0) red[w] = lacc;
        __syncthreads();
        if (tid == 0) {
            float s = 0.0f;
            #pragma unroll
            for (int i = 0; i < 16; i++) s += red[i];
            atomicAdd(out, s * (1.0f / BB));
        }
    }
}

// ---------------------------------------------------------------------------
extern "C" void kernel_launch(void* const* d_in, const int* in_sizes, int n_in,
                              void* d_out, int out_size) {
    int ei = 0, gi = 1;
    if (n_in >= 2 && in_sizes[0] == BB * NPIX) { ei = 1; gi = 0; }

    const float* emb = (const float*)d_in[ei];
    const int*   gt  = (const int*)d_in[gi];
    float* out = (float*)d_out;

    const int NP1 = 2 * P1_NCHUNK;     // 64
    k_zero<<<1, 512>>>(out);
    k_mix<<<NP1, 512>>>(emb, gt, out, 0, -1);                 // prologue
    for (int b = 1; b < BB; b++)
        k_mix<<<NP1 + P2_BLOCKS, 512>>>(emb, gt, out, b, b - 1);
    k_mix<<<P2_BLOCKS, 512>>>(emb, gt, out, -1, BB - 1);      // epilogue
}